// round 1
// baseline (speedup 1.0000x reference)
#include <cuda_runtime.h>
#include <cuda_bf16.h>
#include <math.h>

// ConstrativeLoss: result = (||sum_i n_i||^2 - sum_i n_i.n_i) / (N * T)
// where n_i = x_i / max(||x_i||, 1e-8). Collapses the N^2 D GEMM to O(N D).

#define N_ROWS   16384
#define DIMS     512
#define NB       512      // blocks in kernel 1
#define NT       256      // threads per block
#define NW       8        // warps per block
#define TEMP     0.5
#define EPS      1e-8f

// Fixed scratch (allocation-free). Fully overwritten every launch.
__device__ float  g_spart[NB * DIMS];   // per-block partial of s
__device__ double g_diagpart[NB];       // per-block partial of diag sum

__global__ __launch_bounds__(NT) void k_rows(const float* __restrict__ x) {
    __shared__ float4 s_sh4[NW * (DIMS / 4)];   // 8 warps x 128 float4 = 16 KB
    __shared__ double diag_sh[NW];

    const int w = threadIdx.x >> 5;
    const int l = threadIdx.x & 31;
    const int gwarp = blockIdx.x * NW + w;
    const int nwarps = NB * NW;                 // 4096 warps -> 4 rows each

    float4 acc[4];
    acc[0] = make_float4(0.f, 0.f, 0.f, 0.f);
    acc[1] = acc[0]; acc[2] = acc[0]; acc[3] = acc[0];
    double diag = 0.0;

    for (int row = gwarp; row < N_ROWS; row += nwarps) {
        const float4* xr = reinterpret_cast<const float4*>(x + (size_t)row * DIMS);
        float4 v[4];
        float ss = 0.f;
#pragma unroll
        for (int p = 0; p < 4; p++) {
            v[p] = xr[p * 32 + l];              // coalesced 128B per pass
            ss += v[p].x * v[p].x + v[p].y * v[p].y
                + v[p].z * v[p].z + v[p].w * v[p].w;
        }
        // warp-wide sum of squares (fixed butterfly -> deterministic)
#pragma unroll
        for (int o = 16; o > 0; o >>= 1)
            ss += __shfl_xor_sync(0xFFFFFFFFu, ss, o);

        float nrm = fmaxf(sqrtf(ss), EPS);
        float inv = 1.0f / nrm;
        if (l == 0)
            diag += (double)(ss * inv * inv);   // = n_i . n_i

#pragma unroll
        for (int p = 0; p < 4; p++) {
            acc[p].x += v[p].x * inv;
            acc[p].y += v[p].y * inv;
            acc[p].z += v[p].z * inv;
            acc[p].w += v[p].w * inv;
        }
    }

    // stash per-warp partials (no atomics)
#pragma unroll
    for (int p = 0; p < 4; p++)
        s_sh4[w * 128 + p * 32 + l] = acc[p];
    if (l == 0)
        diag_sh[w] = diag;
    __syncthreads();

    // ordered combine across the 8 warps; first 128 threads own one float4 each
    int t = threadIdx.x;
    if (t < 128) {
        float4 sum = s_sh4[t];
#pragma unroll
        for (int ww = 1; ww < NW; ww++) {
            float4 a = s_sh4[ww * 128 + t];
            sum.x += a.x; sum.y += a.y; sum.z += a.z; sum.w += a.w;
        }
        reinterpret_cast<float4*>(g_spart + (size_t)blockIdx.x * DIMS)[t] = sum;
    }
    if (t == 0) {
        double d = 0.0;
#pragma unroll
        for (int ww = 0; ww < NW; ww++) d += diag_sh[ww];
        g_diagpart[blockIdx.x] = d;
    }
}

__global__ __launch_bounds__(DIMS) void k_final(float* __restrict__ out) {
    const int t = threadIdx.x;

    // deterministic column sum over the 512 block-partials (coalesced in b)
    float s = 0.f;
    for (int b = 0; b < NB; b++)
        s += g_spart[(size_t)b * DIMS + t];

    double val = (double)s * (double)s;      // contributes to ||s||^2
    double dg  = g_diagpart[t];              // NB == DIMS == 512, one each

    __shared__ double sh_v[DIMS];
    __shared__ double sh_d[DIMS];
    sh_v[t] = val;
    sh_d[t] = dg;
    __syncthreads();
#pragma unroll
    for (int o = DIMS / 2; o > 0; o >>= 1) {
        if (t < o) {
            sh_v[t] += sh_v[t + o];
            sh_d[t] += sh_d[t + o];
        }
        __syncthreads();
    }
    if (t == 0) {
        double num = sh_v[0] - sh_d[0];
        out[0] = (float)(num / ((double)N_ROWS * TEMP));
    }
}

extern "C" void kernel_launch(void* const* d_in, const int* in_sizes, int n_in,
                              void* d_out, int out_size) {
    const float* x = (const float*)d_in[0];
    float* out = (float*)d_out;
    k_rows<<<NB, NT>>>(x);
    k_final<<<1, DIMS>>>(out);
}

// round 2
// speedup vs baseline: 1.3563x; 1.3563x over previous
#include <cuda_runtime.h>
#include <cuda_bf16.h>
#include <math.h>

// ConstrativeLoss: result = (||sum_i n_i||^2 - sum_i n_i.n_i) / (N * T)
// where n_i = x_i / max(||x_i||, 1e-8). Collapses the N^2 D GEMM to O(N D).

#define N_ROWS   16384
#define DIMS     512
#define NB       148      // one block per SM
#define NT       512      // 16 warps per block
#define NW       16
#define TEMP     0.5
#define EPS      1e-8f

// Fixed scratch (allocation-free). Fully overwritten every launch.
__device__ float  g_spart[NB * DIMS];   // per-block partial of s  (303 KB)
__device__ double g_diagpart[NB];       // per-block partial of diag sum

__global__ __launch_bounds__(NT) void k_rows(const float* __restrict__ x) {
    __shared__ float4 sh[8 * 128];      // 16 KB staging for the halving tree
    __shared__ double diag_sh[NW];

    const int w = threadIdx.x >> 5;
    const int l = threadIdx.x & 31;
    const int gwarp = blockIdx.x * NW + w;
    const int nwarps = NB * NW;         // 2368 warps -> ~7 rows each

    float4 acc[4];
    acc[0] = make_float4(0.f, 0.f, 0.f, 0.f);
    acc[1] = acc[0]; acc[2] = acc[0]; acc[3] = acc[0];
    double diag = 0.0;

    for (int row = gwarp; row < N_ROWS; row += nwarps) {
        const float4* xr = reinterpret_cast<const float4*>(x + (size_t)row * DIMS);
        float4 v[4];
        float ss = 0.f;
#pragma unroll
        for (int p = 0; p < 4; p++) {
            v[p] = xr[p * 32 + l];      // coalesced 512B per warp per p
            ss += v[p].x * v[p].x + v[p].y * v[p].y
                + v[p].z * v[p].z + v[p].w * v[p].w;
        }
        // warp-wide sum of squares (fixed butterfly -> deterministic)
#pragma unroll
        for (int o = 16; o > 0; o >>= 1)
            ss += __shfl_xor_sync(0xFFFFFFFFu, ss, o);

        float nrm = fmaxf(sqrtf(ss), EPS);
        float inv = 1.0f / nrm;
        if (l == 0)
            diag += (double)(ss * inv * inv);   // = n_i . n_i

#pragma unroll
        for (int p = 0; p < 4; p++) {
            acc[p].x += v[p].x * inv;
            acc[p].y += v[p].y * inv;
            acc[p].z += v[p].z * inv;
            acc[p].w += v[p].w * inv;
        }
    }

    // halving tree across 16 warps (fixed order, deterministic).
    // After the loop, warp 0 holds the full block sum in its acc[].
#pragma unroll
    for (int half = 8; half >= 1; half >>= 1) {
        if (w >= half && w < 2 * half) {
            int dst = (w - half) * 128;
#pragma unroll
            for (int p = 0; p < 4; p++)
                sh[dst + p * 32 + l] = acc[p];
        }
        __syncthreads();
        if (w < half) {
#pragma unroll
            for (int p = 0; p < 4; p++) {
                float4 a = sh[w * 128 + p * 32 + l];
                acc[p].x += a.x; acc[p].y += a.y;
                acc[p].z += a.z; acc[p].w += a.w;
            }
        }
        __syncthreads();
    }

    if (l == 0) diag_sh[w] = diag;
    __syncthreads();

    if (w == 0) {
        float4* gp = reinterpret_cast<float4*>(g_spart + (size_t)blockIdx.x * DIMS);
#pragma unroll
        for (int p = 0; p < 4; p++)
            gp[p * 32 + l] = acc[p];
        if (l == 0) {
            double d = 0.0;
#pragma unroll
            for (int ww = 0; ww < NW; ww++) d += diag_sh[ww];
            g_diagpart[blockIdx.x] = d;
        }
    }
}

__global__ __launch_bounds__(512) void k_final(float* __restrict__ out) {
    const int t = threadIdx.x;
    const int c4 = t & 127;             // float4 column index 0..127
    const int slice = t >> 7;           // 0..3 slice over blocks

    // 4-way sliced column sum over the 148 block-partials, float4-vectorized.
    const float4* sp = reinterpret_cast<const float4*>(g_spart);
    float4 ps = make_float4(0.f, 0.f, 0.f, 0.f);
    for (int b = slice; b < NB; b += 4) {
        float4 a = sp[(size_t)b * 128 + c4];
        ps.x += a.x; ps.y += a.y; ps.z += a.z; ps.w += a.w;
    }

    __shared__ float4 sh[512];
    sh[t] = ps;
    __syncthreads();

    __shared__ double shv[128];
    __shared__ double shd[256];

    if (t < 128) {
        // combine the 4 slices in fixed order -> full column sums s
        float4 s = sh[t];
#pragma unroll
        for (int q = 1; q < 4; q++) {
            float4 a = sh[q * 128 + t];
            s.x += a.x; s.y += a.y; s.z += a.z; s.w += a.w;
        }
        shv[t] = (double)s.x * (double)s.x + (double)s.y * (double)s.y
               + (double)s.z * (double)s.z + (double)s.w * (double)s.w;
    }
    if (t < 256)
        shd[t] = (t < NB) ? g_diagpart[t] : 0.0;
    __syncthreads();

    // deterministic tree reduce: shd over 256, shv over 128
#pragma unroll
    for (int o = 128; o > 0; o >>= 1) {
        if (t < o) shd[t] += shd[t + o];
        if (o <= 64 && t < o) shv[t] += shv[t + o];
        __syncthreads();
    }
    if (t == 0) {
        double num = shv[0] - shd[0];
        out[0] = (float)(num / ((double)N_ROWS * TEMP));
    }
}

extern "C" void kernel_launch(void* const* d_in, const int* in_sizes, int n_in,
                              void* d_out, int out_size) {
    const float* x = (const float*)d_in[0];
    float* out = (float*)d_out;
    k_rows<<<NB, NT>>>(x);
    k_final<<<1, 512>>>(out);
}

// round 3
// speedup vs baseline: 1.3589x; 1.0019x over previous
#include <cuda_runtime.h>
#include <cuda_bf16.h>
#include <math.h>

// ConstrativeLoss: result = (||sum_i n_i||^2 - sum_i n_i.n_i) / (N * T)
// where n_i = x_i / max(||x_i||, 1e-8). O(N D) single fused kernel with
// threadfence last-block reduction (deterministic: int atomic + fixed-order sums).

#define N_ROWS   16384
#define DIMS     512
#define NB       148      // one block per SM, single wave
#define NT       512
#define NW       16
#define TEMP     0.5
#define EPS      1e-8f

// Fixed scratch (allocation-free). Fully overwritten every launch.
__device__ float  g_spart[NB * DIMS];
__device__ double g_diagpart[NB];
__device__ unsigned int g_count;     // zero-init; last block resets each launch

__global__ __launch_bounds__(NT) void k_fused(const float* __restrict__ x,
                                              float* __restrict__ out) {
    __shared__ float4 sh[8 * 128];   // 16 KB staging (tree + final reduce reuse)
    __shared__ double diag_sh[NW];
    __shared__ double shv[128];
    __shared__ double shd[256];
    __shared__ bool   is_last;

    const int w = threadIdx.x >> 5;
    const int l = threadIdx.x & 31;
    const int gwarp = blockIdx.x * NW + w;
    const int nwarps = NB * NW;      // 2368 warps -> 6-7 rows each

    float4 acc[4];
    acc[0] = make_float4(0.f, 0.f, 0.f, 0.f);
    acc[1] = acc[0]; acc[2] = acc[0]; acc[3] = acc[0];
    double diag = 0.0;

    // ---- mainloop: 2 rows per iteration for 8 LDG.128 in flight per warp ----
    int row = gwarp;
    while (row + nwarps < N_ROWS) {
        const float4* r0 = reinterpret_cast<const float4*>(x + (size_t)row * DIMS);
        const float4* r1 = reinterpret_cast<const float4*>(x + (size_t)(row + nwarps) * DIMS);
        float4 v0[4], v1[4];
#pragma unroll
        for (int p = 0; p < 4; p++) v0[p] = r0[p * 32 + l];
#pragma unroll
        for (int p = 0; p < 4; p++) v1[p] = r1[p * 32 + l];

        float ss0 = 0.f, ss1 = 0.f;
#pragma unroll
        for (int p = 0; p < 4; p++) {
            ss0 += v0[p].x * v0[p].x + v0[p].y * v0[p].y
                 + v0[p].z * v0[p].z + v0[p].w * v0[p].w;
            ss1 += v1[p].x * v1[p].x + v1[p].y * v1[p].y
                 + v1[p].z * v1[p].z + v1[p].w * v1[p].w;
        }
#pragma unroll
        for (int o = 16; o > 0; o >>= 1) {
            ss0 += __shfl_xor_sync(0xFFFFFFFFu, ss0, o);
            ss1 += __shfl_xor_sync(0xFFFFFFFFu, ss1, o);
        }
        float inv0 = 1.0f / fmaxf(sqrtf(ss0), EPS);
        float inv1 = 1.0f / fmaxf(sqrtf(ss1), EPS);
        if (l == 0)
            diag += (double)(ss0 * inv0 * inv0) + (double)(ss1 * inv1 * inv1);
#pragma unroll
        for (int p = 0; p < 4; p++) {
            acc[p].x += v0[p].x * inv0 + v1[p].x * inv1;
            acc[p].y += v0[p].y * inv0 + v1[p].y * inv1;
            acc[p].z += v0[p].z * inv0 + v1[p].z * inv1;
            acc[p].w += v0[p].w * inv0 + v1[p].w * inv1;
        }
        row += 2 * nwarps;
    }
    if (row < N_ROWS) {              // tail row (0 or 1 per warp)
        const float4* r0 = reinterpret_cast<const float4*>(x + (size_t)row * DIMS);
        float4 v0[4];
        float ss0 = 0.f;
#pragma unroll
        for (int p = 0; p < 4; p++) {
            v0[p] = r0[p * 32 + l];
            ss0 += v0[p].x * v0[p].x + v0[p].y * v0[p].y
                 + v0[p].z * v0[p].z + v0[p].w * v0[p].w;
        }
#pragma unroll
        for (int o = 16; o > 0; o >>= 1)
            ss0 += __shfl_xor_sync(0xFFFFFFFFu, ss0, o);
        float inv0 = 1.0f / fmaxf(sqrtf(ss0), EPS);
        if (l == 0) diag += (double)(ss0 * inv0 * inv0);
#pragma unroll
        for (int p = 0; p < 4; p++) {
            acc[p].x += v0[p].x * inv0;
            acc[p].y += v0[p].y * inv0;
            acc[p].z += v0[p].z * inv0;
            acc[p].w += v0[p].w * inv0;
        }
    }

    // ---- block combine: halving tree over 16 warps (fixed order) ----
#pragma unroll
    for (int half = 8; half >= 1; half >>= 1) {
        if (w >= half && w < 2 * half) {
            int dst = (w - half) * 128;
#pragma unroll
            for (int p = 0; p < 4; p++)
                sh[dst + p * 32 + l] = acc[p];
        }
        __syncthreads();
        if (w < half) {
#pragma unroll
            for (int p = 0; p < 4; p++) {
                float4 a = sh[w * 128 + p * 32 + l];
                acc[p].x += a.x; acc[p].y += a.y;
                acc[p].z += a.z; acc[p].w += a.w;
            }
        }
        __syncthreads();
    }
    if (l == 0) diag_sh[w] = diag;
    __syncthreads();

    if (w == 0) {
        float4* gp = reinterpret_cast<float4*>(g_spart + (size_t)blockIdx.x * DIMS);
#pragma unroll
        for (int p = 0; p < 4; p++)
            gp[p * 32 + l] = acc[p];
        if (l == 0) {
            double d = 0.0;
#pragma unroll
            for (int ww = 0; ww < NW; ww++) d += diag_sh[ww];
            g_diagpart[blockIdx.x] = d;
        }
    }

    // ---- last-block final reduction ----
    __threadfence();
    if (threadIdx.x == 0) {
        unsigned int old = atomicAdd(&g_count, 1u);
        is_last = (old == NB - 1);
    }
    __syncthreads();

    if (is_last) {
        __threadfence();
        const int t = threadIdx.x;
        const int c4 = t & 127;          // float4 column 0..127
        const int slice = t >> 7;        // 0..3 over blocks; 148/4 = 37 each
        const float4* sp = reinterpret_cast<const float4*>(g_spart);

        float4 pa[4];
        pa[0] = make_float4(0.f, 0.f, 0.f, 0.f);
        pa[1] = pa[0]; pa[2] = pa[0]; pa[3] = pa[0];
#pragma unroll
        for (int i = 0; i < 37; i++) {   // 37 independent LDG.128, 4 acc chains
            int b = slice + 4 * i;
            float4 a = sp[(size_t)b * 128 + c4];
            pa[i & 3].x += a.x; pa[i & 3].y += a.y;
            pa[i & 3].z += a.z; pa[i & 3].w += a.w;
        }
        float4 ps;
        ps.x = (pa[0].x + pa[1].x) + (pa[2].x + pa[3].x);
        ps.y = (pa[0].y + pa[1].y) + (pa[2].y + pa[3].y);
        ps.z = (pa[0].z + pa[1].z) + (pa[2].z + pa[3].z);
        ps.w = (pa[0].w + pa[1].w) + (pa[2].w + pa[3].w);

        sh[t] = ps;
        __syncthreads();

        if (t < 128) {                   // combine 4 slices in fixed order
            float4 s = sh[t];
#pragma unroll
            for (int q = 1; q < 4; q++) {
                float4 a = sh[q * 128 + t];
                s.x += a.x; s.y += a.y; s.z += a.z; s.w += a.w;
            }
            shv[t] = (double)s.x * (double)s.x + (double)s.y * (double)s.y
                   + (double)s.z * (double)s.z + (double)s.w * (double)s.w;
        }
        if (t < 256)
            shd[t] = (t < NB) ? g_diagpart[t] : 0.0;
        __syncthreads();

#pragma unroll
        for (int o = 128; o > 0; o >>= 1) {
            if (t < o) shd[t] += shd[t + o];
            if (o <= 64 && t < o) shv[t] += shv[t + o];
            __syncthreads();
        }
        if (t == 0) {
            double num = shv[0] - shd[0];
            out[0] = (float)(num / ((double)N_ROWS * TEMP));
            g_count = 0;                 // rearm for next graph replay
        }
    }
}

extern "C" void kernel_launch(void* const* d_in, const int* in_sizes, int n_in,
                              void* d_out, int out_size) {
    const float* x = (const float*)d_in[0];
    float* out = (float*)d_out;
    k_fused<<<NB, NT>>>(x, out);
}